// round 16
// baseline (speedup 1.0000x reference)
#include <cuda_runtime.h>
#include <cuda_bf16.h>
#include <cstdint>

// GroupLinear: y[b, g*64+o] = sum_i x[b, g*64+i] * W[g*64+o, g*64+i]
// 64 independent [8192x64] x [64x64]^T GEMMs, fp32 in/out.
//
// mma.sync.m16n8k16 bf16, 2-term split: x = xh+xl (trunc split),
// W = wh+wl (rn split, once per CTA); y ~= xh*wh + xh*wl + xl*wh.
// R16 on R15 (54.8us): x smem path deleted. A-source float2s are loaded
// straight from gmem into a register double-buffer one tile ahead (the A
// lane map is already sector-perfect: 8 rows x 32B per warp instruction).
// Per-tile cp.async, LDS and the barrier all go away -> zero barriers in
// the persistent loop; warps drift and overlap phases.

#define GROUPS     64
#define GS         64
#define BLK_TOK    64
#define THREADS    128
#define IN_CH      4096
#define N_TOKENS   8192
#define NTILES     (N_TOKENS / BLK_TOK)      // 128 tiles per group
#define GRID_X     9                          // 576 CTAs = 1 wave @ 4/SM

// SMEM: W bf16 hi/lo tiles only. Row stride 144 B -> ldmatrix conflict-free.
#define XSTRIDE_H  72
#define ROWB       (XSTRIDE_H * 2)                  // 144
#define SM_WH      0                                 // 9216
#define SM_WL      (SM_WH + GS * ROWB)               // 9216
#define SM_TOTAL   (SM_WL + GS * ROWB)               // 18432

__device__ __forceinline__ uint32_t smem_u32(const void* p) {
    uint32_t a;
    asm("{ .reg .u64 t; cvta.to.shared.u64 t, %1; cvt.u32.u64 %0, t; }"
        : "=r"(a) : "l"(p));
    return a;
}

__device__ __forceinline__ uint32_t pack_bf16(float a, float b) {
    __nv_bfloat162 t = __floats2bfloat162_rn(a, b);
    return *reinterpret_cast<uint32_t*>(&t);
}
// rn split (W only, once per CTA)
__device__ __forceinline__ void split_bf16(float v, float& hi, float& lo) {
    hi = __bfloat162float(__float2bfloat16(v));
    lo = v - hi;
}
__device__ __forceinline__ void split8(const float4& v0, const float4& v1,
                                       uint4& hp, uint4& lp) {
    float h0,l0,h1,l1,h2,l2,h3,l3,h4,l4,h5,l5,h6,l6,h7,l7;
    split_bf16(v0.x,h0,l0); split_bf16(v0.y,h1,l1);
    split_bf16(v0.z,h2,l2); split_bf16(v0.w,h3,l3);
    split_bf16(v1.x,h4,l4); split_bf16(v1.y,h5,l5);
    split_bf16(v1.z,h6,l6); split_bf16(v1.w,h7,l7);
    hp = make_uint4(pack_bf16(h0,h1), pack_bf16(h2,h3),
                    pack_bf16(h4,h5), pack_bf16(h6,h7));
    lp = make_uint4(pack_bf16(l0,l1), pack_bf16(l2,l3),
                    pack_bf16(l4,l5), pack_bf16(l6,l7));
}
// Truncation split for a float2 (A path): hi = top 16 bits (exact trunc),
// lo = exact residual rounded to bf16.
__device__ __forceinline__ void split2t(const float2 v, uint32_t& hp, uint32_t& lp) {
    uint32_t u0 = __float_as_uint(v.x);
    uint32_t u1 = __float_as_uint(v.y);
    hp = __byte_perm(u0, u1, 0x7632);               // {u1.hi16, u0.hi16}
    float h0 = __uint_as_float(u0 & 0xFFFF0000u);
    float h1 = __uint_as_float(u1 & 0xFFFF0000u);
    lp = pack_bf16(v.x - h0, v.y - h1);
}

__device__ __forceinline__ uint4 ldm_x4(uint32_t addr) {
    uint4 r;
    asm volatile("ldmatrix.sync.aligned.m8n8.x4.shared.b16 {%0,%1,%2,%3}, [%4];"
                 : "=r"(r.x), "=r"(r.y), "=r"(r.z), "=r"(r.w) : "r"(addr));
    return r;
}
__device__ __forceinline__ void mma_bf16(float* c, const uint4& a,
                                         uint32_t b0, uint32_t b1) {
    asm volatile(
        "mma.sync.aligned.m16n8k16.row.col.f32.bf16.bf16.f32 "
        "{%0,%1,%2,%3}, {%4,%5,%6,%7}, {%8,%9}, {%0,%1,%2,%3};"
        : "+f"(c[0]), "+f"(c[1]), "+f"(c[2]), "+f"(c[3])
        : "r"(a.x), "r"(a.y), "r"(a.z), "r"(a.w), "r"(b0), "r"(b1));
}

// Per-warp A-source registers for one tile: [kk][{(r,klo),(r+8,klo),(r,khi),(r+8,khi)}]
struct XFrag { float2 v[16]; };

// Load A-source float2s for the tile whose lane base pointer is p.
// Per warp instruction: 8 rows x 32B fully-used sectors.
__device__ __forceinline__ XFrag load_x(const float* __restrict__ p) {
    XFrag f;
    #pragma unroll
    for (int kk = 0; kk < 4; kk++) {
        f.v[kk*4+0] = *reinterpret_cast<const float2*>(p + kk*16);
        f.v[kk*4+1] = *reinterpret_cast<const float2*>(p + kk*16 + 8*IN_CH);
        f.v[kk*4+2] = *reinterpret_cast<const float2*>(p + kk*16 + 8);
        f.v[kk*4+3] = *reinterpret_cast<const float2*>(p + kk*16 + 8*IN_CH + 8);
    }
    return f;
}

__global__ __launch_bounds__(THREADS, 4)
void group_linear_mma(const float* __restrict__ x,
                      const float* __restrict__ w,
                      float* __restrict__ y) {
    extern __shared__ char smem[];
    const uint32_t sb = smem_u32(smem);
    const int tid  = threadIdx.x;
    const int wid  = tid >> 5;
    const int lane = tid & 31;
    const int g    = blockIdx.y;
    const int bx   = blockIdx.x;

    // ---- Prologue: stage W once (rn split), single barrier ----
    {
        #pragma unroll
        for (int r = 0; r < 4; r++) {
            int idx = tid + r * THREADS;            // 0..511
            int row = idx >> 3;                     // 0..63
            int j   = idx & 7;                      // 8-float chunk
            const float4* src = reinterpret_cast<const float4*>(
                w + (size_t)(g * GS + row) * IN_CH + g * GS + j * 8);
            uint4 hp, lp;
            split8(src[0], src[1], hp, lp);
            int off = row * ROWB + j * 16;
            *reinterpret_cast<uint4*>(smem + SM_WH + off) = hp;
            *reinterpret_cast<uint4*>(smem + SM_WL + off) = lp;
        }
    }
    __syncthreads();            // W visible; no barriers after this point.

    const int wrow = wid * 16;                      // warp owns 16 M-rows
    // B ldmatrix lane->addr (mats {n0-7/k0-7, n0-7/k8-15, n8-15/k0-7, n8-15/k8-15})
    const int n_local = (lane >> 4) * 8 + (lane & 7);
    const uint32_t b_addr =
        sb + (uint32_t)(n_local * ROWB + ((lane >> 3) & 1) * 16);
    // A / C lane coordinates (canonical m16n8k16 maps)
    const int ar = wrow + (lane >> 2);              // rows ar, ar+8
    const int ac = (lane & 3) * 2;                  // k cols ac, ac+1 (+8)

    // Per-tile lane base pointer into x
    const float* xbase = x + (size_t)ar * IN_CH + g * GS + ac;
    const size_t tile_step = (size_t)BLK_TOK * IN_CH;

    // ---- Register prefetch pipeline: tile t's x loaded one iter ahead ----
    XFrag xc = load_x(xbase + (size_t)bx * tile_step);

    for (int t = bx; t < NTILES; t += GRID_X) {
        // Prefetch next tile (clamped re-read of current on last iter).
        int tn = (t + GRID_X < NTILES) ? (t + GRID_X) : t;
        XFrag xn = load_x(xbase + (size_t)tn * tile_step);

        // ---- Mainloop: per-kk trunc split + 4 independent acc chains ----
        float acc[8][4];
        #pragma unroll
        for (int nt = 0; nt < 8; nt++)
            #pragma unroll
            for (int i = 0; i < 4; i++)
                acc[nt][i] = 0.0f;

        #pragma unroll
        for (int kk = 0; kk < 4; kk++) {
            const uint32_t kb = kk * 32;            // 16 bf16 = 32 B
            uint4 ah, al;
            split2t(xc.v[kk*4+0], ah.x, al.x);      // rows ar,   k low
            split2t(xc.v[kk*4+1], ah.y, al.y);      // rows ar+8, k low
            split2t(xc.v[kk*4+2], ah.z, al.z);      // rows ar,   k high
            split2t(xc.v[kk*4+3], ah.w, al.w);      // rows ar+8, k high

            #pragma unroll
            for (int npp = 0; npp < 2; npp++) {
                const uint32_t o0 = (npp * 2) * 16 * ROWB + kb;
                const uint32_t o1 = (npp * 2 + 1) * 16 * ROWB + kb;
                uint4 bh0 = ldm_x4(b_addr + SM_WH + o0);
                uint4 bh1 = ldm_x4(b_addr + SM_WH + o1);
                uint4 bl0 = ldm_x4(b_addr + SM_WL + o0);
                uint4 bl1 = ldm_x4(b_addr + SM_WL + o1);
                float* c0 = acc[npp * 4 + 0];
                float* c1 = acc[npp * 4 + 1];
                float* c2 = acc[npp * 4 + 2];
                float* c3 = acc[npp * 4 + 3];
                mma_bf16(c0, ah, bh0.x, bh0.y);     // hi*hi
                mma_bf16(c1, ah, bh0.z, bh0.w);
                mma_bf16(c2, ah, bh1.x, bh1.y);
                mma_bf16(c3, ah, bh1.z, bh1.w);
                mma_bf16(c0, ah, bl0.x, bl0.y);     // hi*lo
                mma_bf16(c1, ah, bl0.z, bl0.w);
                mma_bf16(c2, ah, bl1.x, bl1.y);
                mma_bf16(c3, ah, bl1.z, bl1.w);
                mma_bf16(c0, al, bh0.x, bh0.y);     // lo*hi
                mma_bf16(c1, al, bh0.z, bh0.w);
                mma_bf16(c2, al, bh1.x, bh1.y);
                mma_bf16(c3, al, bh1.z, bh1.w);
            }
        }

        // ---- Epilogue: direct register -> global stores (sector-full) ----
        {
            float* yrow0 = y + (size_t)(t * BLK_TOK + ar) * IN_CH + g * GS + ac;
            float* yrow1 = yrow0 + (size_t)8 * IN_CH;
            #pragma unroll
            for (int cix = 0; cix < 8; cix++) {
                int n0 = (cix >> 2) * 32 + (cix & 3) * 8;
                *reinterpret_cast<float2*>(yrow0 + n0) =
                    make_float2(acc[cix][0], acc[cix][1]);
                *reinterpret_cast<float2*>(yrow1 + n0) =
                    make_float2(acc[cix][2], acc[cix][3]);
            }
        }

        xc = xn;    // advance register pipeline
    }
}

extern "C" void kernel_launch(void* const* d_in, const int* in_sizes, int n_in,
                              void* d_out, int out_size) {
    const float* x = (const float*)d_in[0];   // [8192, 4096] fp32
    const float* w = (const float*)d_in[1];   // [4096, 4096] fp32
    float* y = (float*)d_out;                 // [8192, 4096] fp32

    cudaFuncSetAttribute(group_linear_mma,
                         cudaFuncAttributeMaxDynamicSharedMemorySize, SM_TOTAL);
    dim3 grid(GRID_X, GROUPS);                // (9, 64) persistent CTAs
    group_linear_mma<<<grid, THREADS, SM_TOTAL>>>(x, w, y);
}